// round 9
// baseline (speedup 1.0000x reference)
#include <cuda_runtime.h>
#include <cuda_fp16.h>

// Bilateral filter 9x9, sigma_s=3, sigma_r=0.1, reflect padding, 4096x4096 fp32.
//
// w = exp2( Ls(dx,dy) - K2*(win-c)^2 ),  K2 = 50*log2(e)
// expanded: arg = (-K2*win + a)*win + (b + Ls),  a = 2*K2*c, b = -K2*c^2
//
// Round-9: 4 vertical pixels/thread as two f16x2-ex2 pairs -> MUFU/px stays
// 45 (R8 win) while LDS/px drops 45 -> 27 and ILP doubles (2 MUFU chains,
// 8 accumulator chains) to hold issue efficiency at lower occupancy (R6
// evidence). Inactive rows use compile-time Ls = -1e4 -> f16 exp2 == 0
// exactly; no branches. 128-thread blocks for occupancy granularity.

#define IMG_H 4096
#define IMG_W 4096
#define RAD 4
#define BX 32
#define BY 4
#define PY 4
#define TILE_PH (BY * PY)          // 16 pixel rows per block
#define TW (BX + 2*RAD)            // 40
#define TH (TILE_PH + 2*RAD)       // 24

#define K2F 72.13475204444817f                    /* 50 * log2(e) */
#define LSC (1.4426950408889634f / 18.0f)
#define INACT 1e4f                                 /* Ls = -1e4 -> w == 0 in f16 */

// one MUFU op, two exp2's
__device__ __forceinline__ float2 ex2pair(float a0, float a1) {
    __half2 h = __floats2half2_rn(a0, a1);
    unsigned hu = *reinterpret_cast<unsigned*>(&h);
    unsigned wu;
    asm("ex2.approx.f16x2 %0, %1;" : "=r"(wu) : "r"(hu));
    __half2 w = *reinterpret_cast<__half2*>(&wu);
    return make_float2(__low2float(w), __high2float(w));
}

__device__ __forceinline__ void tap_pair(
    float win,
    float a0, float bt0, float a1, float bt1,
    float& num0, float& den0, float& num1, float& den1)
{
    const float t0 = fmaf(-K2F, win, a0);
    const float g0 = fmaf(win, t0, bt0);
    const float t1 = fmaf(-K2F, win, a1);
    const float g1 = fmaf(win, t1, bt1);
    const float2 w = ex2pair(g0, g1);          // ONE MUFU for both pixels
    num0 = fmaf(w.x, win, num0);
    den0 += w.x;
    num1 = fmaf(w.y, win, num1);
    den1 += w.y;
}

__global__ __launch_bounds__(BX * BY)
void bilateral_kernel(const float* __restrict__ img, float* __restrict__ out) {
    __shared__ float tile[TH][TW];

    const int tx = threadIdx.x;
    const int ty = threadIdx.y;
    const int bx0 = blockIdx.x * BX;
    const int by0 = blockIdx.y * TILE_PH;

    // ---- tile fill: warp-per-row strided, reflect at edges ----
    #pragma unroll
    for (int r = ty; r < TH; r += BY) {
        int gy = by0 + r - RAD;
        gy = (gy < 0) ? -gy : ((gy >= IMG_H) ? (2 * IMG_H - 2 - gy) : gy);
        const float* __restrict__ src = img + (size_t)gy * IMG_W;
        #pragma unroll
        for (int c = tx; c < TW; c += BX) {
            int gx = bx0 + c - RAD;
            gx = (gx < 0) ? -gx : ((gx >= IMG_W) ? (2 * IMG_W - 2 - gx) : gx);
            tile[r][c] = src[gx];
        }
    }
    __syncthreads();

    const int py0 = ty * PY;

    // 4 pixels j=0..3, centers tile[py0+4+j][tx+4]
    float a[PY], b[PY], num[PY], den[PY];
    #pragma unroll
    for (int j = 0; j < PY; j++) {
        const float c = tile[py0 + RAD + j][tx + RAD];
        a[j] = 2.0f * K2F * c;
        b[j] = -K2F * c * c;
        num[j] = 0.f;
        den[j] = 0.f;
    }

    // window rows r = 0..11; pixel j active iff j <= r <= j+8.
    // pair A = (px0, px1) spans rows 0..9; pair B = (px2, px3) rows 2..11.
    #pragma unroll
    for (int r = 0; r < PY + 8; r++) {
        float f[9];
        #pragma unroll
        for (int k = 0; k < 9; k++) f[k] = tile[py0 + r][tx + k];

        // compile-time spatial row terms (INACT when row outside a pixel's window)
        const float dqA0 = (r <= 8)            ? (float)((r - 4) * (r - 4)) : INACT;
        const float dqA1 = (r >= 1 && r <= 9)  ? (float)((r - 5) * (r - 5)) : INACT;
        const float dqB0 = (r >= 2 && r <= 10) ? (float)((r - 6) * (r - 6)) : INACT;
        const float dqB1 = (r >= 3)            ? (float)((r - 7) * (r - 7)) : INACT;

        if (r <= 9) {      // pair A
            #pragma unroll
            for (int k = 0; k < 9; k++) {
                const float kq = (float)((k - 4) * (k - 4));
                tap_pair(f[k],
                         a[0], b[0] - (kq + dqA0) * LSC,
                         a[1], b[1] - (kq + dqA1) * LSC,
                         num[0], den[0], num[1], den[1]);
            }
        }
        if (r >= 2) {      // pair B
            #pragma unroll
            for (int k = 0; k < 9; k++) {
                const float kq = (float)((k - 4) * (k - 4));
                tap_pair(f[k],
                         a[2], b[2] - (kq + dqB0) * LSC,
                         a[3], b[3] - (kq + dqB1) * LSC,
                         num[2], den[2], num[3], den[3]);
            }
        }
    }

    size_t o = (size_t)(by0 + py0) * IMG_W + bx0 + tx;
    #pragma unroll
    for (int j = 0; j < PY; j++) {
        out[o] = __fdividef(num[j], den[j]);
        o += IMG_W;
    }
}

extern "C" void kernel_launch(void* const* d_in, const int* in_sizes, int n_in,
                              void* d_out, int out_size) {
    const float* img = (const float*)d_in[0];
    float* out = (float*)d_out;
    dim3 block(BX, BY);
    dim3 grid(IMG_W / BX, IMG_H / TILE_PH);
    bilateral_kernel<<<grid, block>>>(img, out);
}

// round 10
// speedup vs baseline: 1.1766x; 1.1766x over previous
#include <cuda_runtime.h>
#include <cuda_fp16.h>

// Bilateral filter 9x9, sigma_s=3, sigma_r=0.1, reflect padding, 4096x4096 fp32.
//
// w = exp2( Ls(dx,dy) - K2*(win-c)^2 ),  K2 = 50*log2(e)
// expanded: arg = (-K2*win + a)*win + (b + Ls),  a = 2*K2*c, b = -K2*c^2
//
// Round-10: 2x2 pixels/thread. Window row union (10 floats) loaded as 5
// aligned LDS.64 shared by all 4 pixels (LDS/px 45 -> 12.5; halves used as
// scalars, no marshalling). f16x2 ex2 pairing with ZERO wasted taps:
// interior rows pair vertically (shared win), edge rows r=0/9 pair the two
// horizontal pixels (one packed MUFU, distinct win). 40.5 MUFU/px.
// f32 args + f32 accumulation (precision), 128-thread blocks, no reg cap.

#define IMG_H 4096
#define IMG_W 4096
#define RAD 4
#define BX 32
#define BY 4
#define PX 2
#define PY 2
#define TILE_PW (BX * PX)          // 64 pixel cols per block
#define TILE_PH (BY * PY)          // 8 pixel rows per block
#define TW (TILE_PW + 2*RAD)       // 72 floats/row (288B, 8B-aligned stride)
#define TH (TILE_PH + 2*RAD)       // 16 rows

#define K2F 72.13475204444817f                    /* 50 * log2(e) */
#define LSC (1.4426950408889634f / 18.0f)

// one MUFU op, two exp2's (f32 in/out, f16 internally)
__device__ __forceinline__ float2 ex2pair(float a0, float a1) {
    __half2 h = __floats2half2_rn(a0, a1);
    unsigned hu = *reinterpret_cast<unsigned*>(&h);
    unsigned wu;
    asm("ex2.approx.f16x2 %0, %1;" : "=r"(wu) : "r"(hu));
    __half2 w = *reinterpret_cast<__half2*>(&wu);
    return make_float2(__low2float(w), __high2float(w));
}

__global__ __launch_bounds__(BX * BY)
void bilateral_kernel(const float* __restrict__ img, float* __restrict__ out) {
    __shared__ __align__(16) float tile[TH][TW];

    const int tx = threadIdx.x;
    const int ty = threadIdx.y;
    const int bx0 = blockIdx.x * TILE_PW;
    const int by0 = blockIdx.y * TILE_PH;

    // ---- tile fill: strided, reflect at edges ----
    #pragma unroll
    for (int r = ty; r < TH; r += BY) {
        int gy = by0 + r - RAD;
        gy = (gy < 0) ? -gy : ((gy >= IMG_H) ? (2 * IMG_H - 2 - gy) : gy);
        const float* __restrict__ src = img + (size_t)gy * IMG_W;
        #pragma unroll
        for (int c = tx; c < TW; c += BX) {
            int gx = bx0 + c - RAD;
            gx = (gx < 0) ? -gx : ((gx >= IMG_W) ? (2 * IMG_W - 2 - gx) : gx);
            tile[r][c] = src[gx];
        }
    }
    __syncthreads();

    const int cb  = tx * PX;   // even -> aligned float2 window loads
    const int py0 = ty * PY;

    // pixels p = j*2+i, center tile[py0+4+j][cb+4+i]
    float a[4], b[4], num[4], den[4];
    #pragma unroll
    for (int j = 0; j < PY; j++) {
        #pragma unroll
        for (int i = 0; i < PX; i++) {
            const float c = tile[py0 + RAD + j][cb + RAD + i];
            const int p = j * 2 + i;
            a[p] = 2.0f * K2F * c;
            b[p] = -K2F * c * c;
            num[p] = 0.f;
            den[p] = 0.f;
        }
    }

    // window rows r = 0..9; px-row j active iff j <= r <= j+8
    #pragma unroll
    for (int r = 0; r < 10; r++) {
        // 10-float union row as 5 aligned LDS.64
        float f[10];
        const float2* __restrict__ rp =
            reinterpret_cast<const float2*>(&tile[py0 + r][cb]);
        #pragma unroll
        for (int q = 0; q < 5; q++) {
            const float2 v = rp[q];
            f[2 * q]     = v.x;
            f[2 * q + 1] = v.y;
        }

        if (r == 0 || r == 9) {
            // only one pixel row active -> pair HORIZONTALLY (p0=left, p1=right)
            const int p0 = (r == 0) ? 0 : 2;   // j = 0 or 1
            const int p1 = p0 + 1;
            #pragma unroll
            for (int k = 0; k < 9; k++) {
                const float Ls = -(float)((k - 4) * (k - 4) + 16) * LSC;
                const float w0 = f[k];
                const float w1 = f[k + 1];
                const float g0 = fmaf(w0, fmaf(-K2F, w0, a[p0]), b[p0] + Ls);
                const float g1 = fmaf(w1, fmaf(-K2F, w1, a[p1]), b[p1] + Ls);
                const float2 w = ex2pair(g0, g1);        // ONE MUFU
                num[p0] = fmaf(w.x, w0, num[p0]);
                den[p0] += w.x;
                num[p1] = fmaf(w.y, w1, num[p1]);
                den[p1] += w.y;
            }
        } else {
            // both pixel rows active -> pair VERTICALLY per column (shared win)
            const int dq0 = (r - 4) * (r - 4);   // j=0 row term (compile-time)
            const int dq1 = (r - 5) * (r - 5);   // j=1
            #pragma unroll
            for (int i = 0; i < PX; i++) {
                const int pT = i;        // (j=0, i)
                const int pB = 2 + i;    // (j=1, i)
                #pragma unroll
                for (int k = 0; k < 9; k++) {
                    const float win = f[i + k];
                    const int   kq  = (k - 4) * (k - 4);
                    const float g0 = fmaf(win, fmaf(-K2F, win, a[pT]),
                                          b[pT] - (float)(kq + dq0) * LSC);
                    const float g1 = fmaf(win, fmaf(-K2F, win, a[pB]),
                                          b[pB] - (float)(kq + dq1) * LSC);
                    const float2 w = ex2pair(g0, g1);    // ONE MUFU, both rows
                    num[pT] = fmaf(w.x, win, num[pT]);
                    den[pT] += w.x;
                    num[pB] = fmaf(w.y, win, num[pB]);
                    den[pB] += w.y;
                }
            }
        }
    }

    // 2x2 output, one aligned float2 store per pixel row
    #pragma unroll
    for (int j = 0; j < PY; j++) {
        float2 o;
        o.x = __fdividef(num[j * 2 + 0], den[j * 2 + 0]);
        o.y = __fdividef(num[j * 2 + 1], den[j * 2 + 1]);
        *reinterpret_cast<float2*>(
            &out[(size_t)(by0 + py0 + j) * IMG_W + bx0 + cb]) = o;
    }
}

extern "C" void kernel_launch(void* const* d_in, const int* in_sizes, int n_in,
                              void* d_out, int out_size) {
    const float* img = (const float*)d_in[0];
    float* out = (float*)d_out;
    dim3 block(BX, BY);
    dim3 grid(IMG_W / TILE_PW, IMG_H / TILE_PH);
    bilateral_kernel<<<grid, block>>>(img, out);
}

// round 11
// speedup vs baseline: 1.2185x; 1.0356x over previous
#include <cuda_runtime.h>
#include <cuda_fp16.h>

// Bilateral filter 9x9, sigma_s=3, sigma_r=0.1, reflect padding, 4096x4096 fp32.
//
// w = exp2( Ls(dx,dy) - K2*(win-c)^2 ),  K2 = 50*log2(e)
// expanded: arg = (-K2*win + a)*win + (b + Ls),  a = 2*K2*c, b = -K2*c^2
//
// Round-11: identical to R10 (best, 326us) except __launch_bounds__(128, 6):
// cap regs 95 -> 85 to fit 6 blocks/SM (occ 30.3% -> 37.5%). The 95 regs were
// scheduler lookahead, not live data (~40), so the cap trims pipelining, not
// spills (R7's spill came from capping BELOW live demand).
//
// Geometry: 2x2 px/thread; window row union (10 floats) = 5 aligned LDS.64
// shared by 4 pixels; f16x2 ex2 pairing, zero wasted taps (interior rows pair
// vertically on shared win, edge rows pair horizontally). 40.5 MUFU/px.

#define IMG_H 4096
#define IMG_W 4096
#define RAD 4
#define BX 32
#define BY 4
#define PX 2
#define PY 2
#define TILE_PW (BX * PX)          // 64 pixel cols per block
#define TILE_PH (BY * PY)          // 8 pixel rows per block
#define TW (TILE_PW + 2*RAD)       // 72 floats/row (288B, 8B-aligned stride)
#define TH (TILE_PH + 2*RAD)       // 16 rows

#define K2F 72.13475204444817f                    /* 50 * log2(e) */
#define LSC (1.4426950408889634f / 18.0f)

// one MUFU op, two exp2's (f32 in/out, f16 internally)
__device__ __forceinline__ float2 ex2pair(float a0, float a1) {
    __half2 h = __floats2half2_rn(a0, a1);
    unsigned hu = *reinterpret_cast<unsigned*>(&h);
    unsigned wu;
    asm("ex2.approx.f16x2 %0, %1;" : "=r"(wu) : "r"(hu));
    __half2 w = *reinterpret_cast<__half2*>(&wu);
    return make_float2(__low2float(w), __high2float(w));
}

__global__ __launch_bounds__(BX * BY, 6)
void bilateral_kernel(const float* __restrict__ img, float* __restrict__ out) {
    __shared__ __align__(16) float tile[TH][TW];

    const int tx = threadIdx.x;
    const int ty = threadIdx.y;
    const int bx0 = blockIdx.x * TILE_PW;
    const int by0 = blockIdx.y * TILE_PH;

    // ---- tile fill: strided, reflect at edges ----
    #pragma unroll
    for (int r = ty; r < TH; r += BY) {
        int gy = by0 + r - RAD;
        gy = (gy < 0) ? -gy : ((gy >= IMG_H) ? (2 * IMG_H - 2 - gy) : gy);
        const float* __restrict__ src = img + (size_t)gy * IMG_W;
        #pragma unroll
        for (int c = tx; c < TW; c += BX) {
            int gx = bx0 + c - RAD;
            gx = (gx < 0) ? -gx : ((gx >= IMG_W) ? (2 * IMG_W - 2 - gx) : gx);
            tile[r][c] = src[gx];
        }
    }
    __syncthreads();

    const int cb  = tx * PX;   // even -> aligned float2 window loads
    const int py0 = ty * PY;

    // pixels p = j*2+i, center tile[py0+4+j][cb+4+i]
    float a[4], b[4], num[4], den[4];
    #pragma unroll
    for (int j = 0; j < PY; j++) {
        #pragma unroll
        for (int i = 0; i < PX; i++) {
            const float c = tile[py0 + RAD + j][cb + RAD + i];
            const int p = j * 2 + i;
            a[p] = 2.0f * K2F * c;
            b[p] = -K2F * c * c;
            num[p] = 0.f;
            den[p] = 0.f;
        }
    }

    // window rows r = 0..9; px-row j active iff j <= r <= j+8
    #pragma unroll
    for (int r = 0; r < 10; r++) {
        // 10-float union row as 5 aligned LDS.64
        float f[10];
        const float2* __restrict__ rp =
            reinterpret_cast<const float2*>(&tile[py0 + r][cb]);
        #pragma unroll
        for (int q = 0; q < 5; q++) {
            const float2 v = rp[q];
            f[2 * q]     = v.x;
            f[2 * q + 1] = v.y;
        }

        if (r == 0 || r == 9) {
            // only one pixel row active -> pair HORIZONTALLY (p0=left, p1=right)
            const int p0 = (r == 0) ? 0 : 2;   // j = 0 or 1
            const int p1 = p0 + 1;
            #pragma unroll
            for (int k = 0; k < 9; k++) {
                const float Ls = -(float)((k - 4) * (k - 4) + 16) * LSC;
                const float w0 = f[k];
                const float w1 = f[k + 1];
                const float g0 = fmaf(w0, fmaf(-K2F, w0, a[p0]), b[p0] + Ls);
                const float g1 = fmaf(w1, fmaf(-K2F, w1, a[p1]), b[p1] + Ls);
                const float2 w = ex2pair(g0, g1);        // ONE MUFU
                num[p0] = fmaf(w.x, w0, num[p0]);
                den[p0] += w.x;
                num[p1] = fmaf(w.y, w1, num[p1]);
                den[p1] += w.y;
            }
        } else {
            // both pixel rows active -> pair VERTICALLY per column (shared win)
            const int dq0 = (r - 4) * (r - 4);   // j=0 row term (compile-time)
            const int dq1 = (r - 5) * (r - 5);   // j=1
            #pragma unroll
            for (int i = 0; i < PX; i++) {
                const int pT = i;        // (j=0, i)
                const int pB = 2 + i;    // (j=1, i)
                #pragma unroll
                for (int k = 0; k < 9; k++) {
                    const float win = f[i + k];
                    const int   kq  = (k - 4) * (k - 4);
                    const float g0 = fmaf(win, fmaf(-K2F, win, a[pT]),
                                          b[pT] - (float)(kq + dq0) * LSC);
                    const float g1 = fmaf(win, fmaf(-K2F, win, a[pB]),
                                          b[pB] - (float)(kq + dq1) * LSC);
                    const float2 w = ex2pair(g0, g1);    // ONE MUFU, both rows
                    num[pT] = fmaf(w.x, win, num[pT]);
                    den[pT] += w.x;
                    num[pB] = fmaf(w.y, win, num[pB]);
                    den[pB] += w.y;
                }
            }
        }
    }

    // 2x2 output, one aligned float2 store per pixel row
    #pragma unroll
    for (int j = 0; j < PY; j++) {
        float2 o;
        o.x = __fdividef(num[j * 2 + 0], den[j * 2 + 0]);
        o.y = __fdividef(num[j * 2 + 1], den[j * 2 + 1]);
        *reinterpret_cast<float2*>(
            &out[(size_t)(by0 + py0 + j) * IMG_W + bx0 + cb]) = o;
    }
}

extern "C" void kernel_launch(void* const* d_in, const int* in_sizes, int n_in,
                              void* d_out, int out_size) {
    const float* img = (const float*)d_in[0];
    float* out = (float*)d_out;
    dim3 block(BX, BY);
    dim3 grid(IMG_W / TILE_PW, IMG_H / TILE_PH);
    bilateral_kernel<<<grid, block>>>(img, out);
}